// round 3
// baseline (speedup 1.0000x reference)
#include <cuda_runtime.h>

// ---------------------------------------------------------------------------
// Problem constants: B=8, TQ=TK=2048, F=1024, H=1024
// ---------------------------------------------------------------------------
// Scratch (static __device__ arrays: allocation-free per harness rules)
static __device__ float g_Q[16384LL * 1024];        // 64 MB
static __device__ float g_K[16384LL * 1024];        // 64 MB
static __device__ float g_V[16384LL * 1024];        // 64 MB
static __device__ float g_S[8LL * 2048 * 2048];     // 128 MB (scores, then probs in-place)
static __device__ int   g_mask_mode;                // 0=u8, 1=i32, 2=f32

// ---------------------------------------------------------------------------
// Packed fp32x2 helpers (Blackwell sm_100+/103a): 2 FMAs per issue slot
// ---------------------------------------------------------------------------
__device__ __forceinline__ unsigned long long f2_dup(float x) {
    unsigned long long r;
    unsigned int xi = __float_as_uint(x);
    asm("mov.b64 %0, {%1, %2};" : "=l"(r) : "r"(xi), "r"(xi));
    return r;
}
__device__ __forceinline__ unsigned long long f2_fma(unsigned long long a,
                                                     unsigned long long b,
                                                     unsigned long long c) {
    unsigned long long d;
    asm("fma.rn.f32x2 %0, %1, %2, %3;" : "=l"(d) : "l"(a), "l"(b), "l"(c));
    return d;
}
__device__ __forceinline__ float2 f2_unpack(unsigned long long v) {
    unsigned int lo, hi;
    asm("mov.b64 {%0, %1}, %2;" : "=r"(lo), "=r"(hi) : "l"(v));
    return make_float2(__uint_as_float(lo), __uint_as_float(hi));
}

// ---------------------------------------------------------------------------
// Tiled fp32 GEMM, f32x2 inner product.
//   C[m,n] = alpha * sum_k A[m,k] * B'[k,n] (+ bias[n])
//   BT=false: B is [K,N] row-major.  BT=true: B is [N,K] row-major (A @ B^T).
// Block tile 128x128, K-step 16, 256 threads, 8x8 microtile per thread.
// All dims are exact multiples of tile sizes for this problem (no bounds checks).
// ---------------------------------------------------------------------------
#define BM 128
#define BN 128
#define BK 16
#define PAD 4
#define BMP (BM + PAD)
#define BNP (BN + PAD)

template <bool BT>
__global__ void __launch_bounds__(256, 2)
gemm_kernel(const float* __restrict__ A, const float* __restrict__ B,
            const float* __restrict__ bias, float* __restrict__ C,
            int M, int N, int K, float alpha,
            long long sA, long long sB, long long sC)
{
    __shared__ float As[2][BK][BMP];
    __shared__ float Bs[2][BK][BNP];

    const long long bz = blockIdx.z;
    A += bz * sA;
    B += bz * sB;
    C += bz * sC;

    const int m0  = blockIdx.y * BM;
    const int n0  = blockIdx.x * BN;
    const int tid = threadIdx.x;

    // A tile loader indices: 128 rows x 16 cols, 2 float4 per thread
    const int a_r = tid >> 2;            // 0..63 (and +64)
    const int a_c = (tid & 3) << 2;      // 0,4,8,12
    const float* Ag = A + (long long)(m0 + a_r) * K + a_c;

    // B tile loader indices
    int b_r, b_c;
    const float* Bg;
    if (BT) {  // B[N,K]: load like A, store transposed
        b_r = tid >> 2;                  // 0..63 (and +64)
        b_c = (tid & 3) << 2;
        Bg  = B + (long long)(n0 + b_r) * K + b_c;
    } else {   // B[K,N]: 16 rows x 128 cols
        b_r = tid >> 5;                  // 0..7 (and +8)
        b_c = (tid & 31) << 2;           // 0..124
        Bg  = B + (long long)b_r * N + n0 + b_c;
    }

    const int tm = (tid >> 4) << 3;      // 0..120
    const int tn = (tid & 15) << 3;      // 0..120

    unsigned long long acc[4][8];
#pragma unroll
    for (int i = 0; i < 4; i++)
#pragma unroll
        for (int j = 0; j < 8; j++) acc[i][j] = 0ULL;

    const int nt = K / BK;

    float4 va0, va1, vb0, vb1;

    auto loadRegs = [&](int t) {
        const long long ko = (long long)t * BK;
        va0 = *(const float4*)(Ag + ko);
        va1 = *(const float4*)(Ag + ko + 64LL * K);
        if (BT) {
            vb0 = *(const float4*)(Bg + ko);
            vb1 = *(const float4*)(Bg + ko + 64LL * K);
        } else {
            vb0 = *(const float4*)(Bg + ko * N);
            vb1 = *(const float4*)(Bg + (ko + 8) * N);
        }
    };
    auto storeRegs = [&](int buf) {
        As[buf][a_c + 0][a_r] = va0.x;
        As[buf][a_c + 1][a_r] = va0.y;
        As[buf][a_c + 2][a_r] = va0.z;
        As[buf][a_c + 3][a_r] = va0.w;
        As[buf][a_c + 0][a_r + 64] = va1.x;
        As[buf][a_c + 1][a_r + 64] = va1.y;
        As[buf][a_c + 2][a_r + 64] = va1.z;
        As[buf][a_c + 3][a_r + 64] = va1.w;
        if (BT) {
            Bs[buf][b_c + 0][b_r] = vb0.x;
            Bs[buf][b_c + 1][b_r] = vb0.y;
            Bs[buf][b_c + 2][b_r] = vb0.z;
            Bs[buf][b_c + 3][b_r] = vb0.w;
            Bs[buf][b_c + 0][b_r + 64] = vb1.x;
            Bs[buf][b_c + 1][b_r + 64] = vb1.y;
            Bs[buf][b_c + 2][b_r + 64] = vb1.z;
            Bs[buf][b_c + 3][b_r + 64] = vb1.w;
        } else {
            *(float4*)&Bs[buf][b_r][b_c]     = vb0;
            *(float4*)&Bs[buf][b_r + 8][b_c] = vb1;
        }
    };

    loadRegs(0);

    for (int t = 0; t < nt; t++) {
        const int cur = t & 1;
        storeRegs(cur);
        __syncthreads();
        if (t + 1 < nt) loadRegs(t + 1);

#pragma unroll
        for (int kk = 0; kk < BK; kk++) {
            unsigned long long a2[4];
#pragma unroll
            for (int i = 0; i < 4; i++)
                a2[i] = *(const unsigned long long*)&As[cur][kk][tm + 2 * i];

            float4 bA = *(const float4*)&Bs[cur][kk][tn];
            float4 bB = *(const float4*)&Bs[cur][kk][tn + 4];
            unsigned long long bd[8];
            bd[0] = f2_dup(bA.x); bd[1] = f2_dup(bA.y);
            bd[2] = f2_dup(bA.z); bd[3] = f2_dup(bA.w);
            bd[4] = f2_dup(bB.x); bd[5] = f2_dup(bB.y);
            bd[6] = f2_dup(bB.z); bd[7] = f2_dup(bB.w);

#pragma unroll
            for (int i = 0; i < 4; i++)
#pragma unroll
                for (int j = 0; j < 8; j++)
                    acc[i][j] = f2_fma(a2[i], bd[j], acc[i][j]);
        }
    }

    // Epilogue: alpha * acc (+ bias), vectorized stores
    float bj[8];
#pragma unroll
    for (int j = 0; j < 8; j++) bj[j] = bias ? bias[n0 + tn + j] : 0.0f;

#pragma unroll
    for (int i = 0; i < 4; i++) {
        float lo[8], hi[8];
#pragma unroll
        for (int j = 0; j < 8; j++) {
            float2 v = f2_unpack(acc[i][j]);
            lo[j] = v.x * alpha + bj[j];
            hi[j] = v.y * alpha + bj[j];
        }
        const long long r0 = (long long)(m0 + tm + 2 * i) * N + n0 + tn;
        const long long r1 = r0 + N;
        *(float4*)&C[r0]     = make_float4(lo[0], lo[1], lo[2], lo[3]);
        *(float4*)&C[r0 + 4] = make_float4(lo[4], lo[5], lo[6], lo[7]);
        *(float4*)&C[r1]     = make_float4(hi[0], hi[1], hi[2], hi[3]);
        *(float4*)&C[r1 + 4] = make_float4(hi[4], hi[5], hi[6], hi[7]);
    }
}

// ---------------------------------------------------------------------------
// Mask dtype detection (bool can arrive as u8, i32 or f32 depending on the
// harness conversion). Deterministic function of the input buffer.
// ---------------------------------------------------------------------------
__global__ void detect_mask_kernel(const unsigned char* __restrict__ m)
{
    __shared__ int bad_i32, bad_f32;
    if (threadIdx.x == 0) { bad_i32 = 0; bad_f32 = 0; }
    __syncthreads();
    const unsigned int* w = (const unsigned int*)m;
    for (int i = threadIdx.x; i < 2048; i += 256) {
        unsigned int x = w[i];
        if (x != 0u && x != 1u)          bad_i32 = 1;  // benign race: all write 1
        if (x != 0u && x != 0x3F800000u) bad_f32 = 1;
    }
    __syncthreads();
    if (threadIdx.x == 0)
        g_mask_mode = bad_i32 ? (bad_f32 ? 0 : 2) : 1;
}

// ---------------------------------------------------------------------------
// Masked softmax over rows of S [B*TQ, 2048], in place. P = 0 where masked.
// One block (256 threads) per row, 8 elements per thread kept in registers.
// ---------------------------------------------------------------------------
__global__ void __launch_bounds__(256)
softmax_kernel(float* __restrict__ S, const void* __restrict__ maskv)
{
    const int TK = 2048;
    const long long row  = blockIdx.x;
    const long long base = row * TK;
    float* s = S + base;
    const int tid  = threadIdx.x;
    const int mode = g_mask_mode;

    float v[8];
    bool  keep[8];
#pragma unroll
    for (int i = 0; i < 8; i++) {
        const int idx = tid + i * 256;
        v[i] = s[idx];
        bool kp;
        if (mode == 1)      kp = ((const int*)maskv)[base + idx] != 0;
        else if (mode == 2) kp = ((const float*)maskv)[base + idx] != 0.0f;
        else                kp = ((const unsigned char*)maskv)[base + idx] != 0;
        keep[i] = kp;
    }

    float mx = -3.0e38f;
#pragma unroll
    for (int i = 0; i < 8; i++)
        if (keep[i]) mx = fmaxf(mx, v[i]);

    __shared__ float red[8];
#pragma unroll
    for (int o = 16; o > 0; o >>= 1)
        mx = fmaxf(mx, __shfl_xor_sync(0xffffffffu, mx, o));
    if ((tid & 31) == 0) red[tid >> 5] = mx;
    __syncthreads();
    float bm = red[0];
#pragma unroll
    for (int i = 1; i < 8; i++) bm = fmaxf(bm, red[i]);

    float sum = 0.0f;
#pragma unroll
    for (int i = 0; i < 8; i++) {
        const float e = keep[i] ? __expf(v[i] - bm) : 0.0f;
        v[i] = e;
        sum += e;
    }
#pragma unroll
    for (int o = 16; o > 0; o >>= 1)
        sum += __shfl_xor_sync(0xffffffffu, sum, o);
    __syncthreads();  // red reuse
    if ((tid & 31) == 0) red[tid >> 5] = sum;
    __syncthreads();
    float ts = 0.0f;
#pragma unroll
    for (int i = 0; i < 8; i++) ts += red[i];

    const float inv = 1.0f / ts;
#pragma unroll
    for (int i = 0; i < 8; i++)
        s[tid + i * 256] = v[i] * inv;
}

// ---------------------------------------------------------------------------
// kernel_launch: 3 projection GEMMs -> QK^T -> masked softmax -> PV
// ---------------------------------------------------------------------------
extern "C" void kernel_launch(void* const* d_in, const int* in_sizes, int n_in,
                              void* d_out, int out_size)
{
    (void)in_sizes; (void)n_in; (void)out_size;

    const float* query = (const float*)d_in[0];
    const float* enc   = (const float*)d_in[1];
    const unsigned char* mask = (const unsigned char*)d_in[2];
    const float* Wq = (const float*)d_in[3];
    const float* bq = (const float*)d_in[4];
    const float* Wk = (const float*)d_in[5];
    const float* bk = (const float*)d_in[6];
    const float* Wv = (const float*)d_in[7];
    const float* bv = (const float*)d_in[8];
    float* out = (float*)d_out;

    float *Qp, *Kp, *Vp, *Sp;
    cudaGetSymbolAddress((void**)&Qp, g_Q);
    cudaGetSymbolAddress((void**)&Kp, g_K);
    cudaGetSymbolAddress((void**)&Vp, g_V);
    cudaGetSymbolAddress((void**)&Sp, g_S);

    const int Bb = 8, T = 2048, F = 1024, H = 1024;
    const int M = Bb * T;  // 16384

    dim3 blk(256);

    // Projections: [M,F] @ [F,H] + bias
    dim3 gp(H / BN, M / BM, 1);
    gemm_kernel<false><<<gp, blk>>>(enc,   Wk, bk, Kp, M, H, F, 1.0f, 0, 0, 0);
    gemm_kernel<false><<<gp, blk>>>(enc,   Wv, bv, Vp, M, H, F, 1.0f, 0, 0, 0);
    gemm_kernel<false><<<gp, blk>>>(query, Wq, bq, Qp, M, H, F, 1.0f, 0, 0, 0);

    detect_mask_kernel<<<1, 256>>>(mask);

    // Scores: per batch, S = (Q @ K^T) / sqrt(H);  1/sqrt(1024) = 0.03125
    dim3 gs(T / BN, T / BM, Bb);
    gemm_kernel<true><<<gs, blk>>>(Qp, Kp, nullptr, Sp, T, T, H, 0.03125f,
                                   (long long)T * H, (long long)T * H,
                                   (long long)T * T);

    // Masked softmax in place
    softmax_kernel<<<Bb * T, blk>>>(Sp, (const void*)mask);

    // Output: per batch, O = P @ V
    dim3 go(H / BN, T / BM, Bb);
    gemm_kernel<false><<<go, blk>>>(Sp, Vp, nullptr, out, T, H, T, 1.0f,
                                    (long long)T * T, (long long)T * H,
                                    (long long)T * H);
}

// round 5
// speedup vs baseline: 2.0404x; 2.0404x over previous
#include <cuda_runtime.h>
#include <cuda_bf16.h>

typedef __nv_bfloat16 bf16;
typedef unsigned int u32;
typedef unsigned long long u64;

// ---------------------------------------------------------------------------
// Problem constants: B=8, TQ=TK=2048, F=1024, H=1024
// ---------------------------------------------------------------------------
#define MTOT (16384LL * 1024)

static __device__ bf16  g_Ehi[MTOT],  g_Elo[MTOT];
static __device__ bf16  g_Xhi[MTOT],  g_Xlo[MTOT];
static __device__ bf16  g_Wq_hi[1024*1024], g_Wq_lo[1024*1024];
static __device__ bf16  g_Wk_hi[1024*1024], g_Wk_lo[1024*1024];
static __device__ bf16  g_Wv_hi[1024*1024], g_Wv_lo[1024*1024];
static __device__ bf16  g_Qhi[MTOT],  g_Qlo[MTOT];
static __device__ bf16  g_Khi[MTOT],  g_Klo[MTOT];
static __device__ bf16  g_Vhi[MTOT],  g_Vlo[MTOT];          // V [b*2048+t][1024]
static __device__ float g_S[8LL * 2048 * 2048];
static __device__ bf16  g_Phi[8LL * 2048 * 2048], g_Plo[8LL * 2048 * 2048];
static __device__ int   g_mask_mode;

// ---------------------------------------------------------------------------
// PTX helpers (all sm_80-era features; legal under generic compute_103 target)
// ---------------------------------------------------------------------------
__device__ __forceinline__ u32 smem_u32(const void* p) {
    u32 a;
    asm("{ .reg .u64 t; cvta.to.shared.u64 t, %1; cvt.u32.u64 %0, t; }"
        : "=r"(a) : "l"(p));
    return a;
}
#define CP_ASYNC16(dst, src) \
    asm volatile("cp.async.cg.shared.global [%0], [%1], 16;" \
                 :: "r"(dst), "l"(src) : "memory")
#define CP_COMMIT() asm volatile("cp.async.commit_group;" ::: "memory")
#define CP_WAIT1()  asm volatile("cp.async.wait_group 1;" ::: "memory")

__device__ __forceinline__ void ldsm_x4(u32& r0, u32& r1, u32& r2, u32& r3, u32 a) {
    asm volatile("ldmatrix.sync.aligned.m8n8.x4.shared.b16 {%0,%1,%2,%3}, [%4];"
                 : "=r"(r0), "=r"(r1), "=r"(r2), "=r"(r3) : "r"(a));
}
__device__ __forceinline__ void ldsm_x2(u32& r0, u32& r1, u32 a) {
    asm volatile("ldmatrix.sync.aligned.m8n8.x2.shared.b16 {%0,%1}, [%2];"
                 : "=r"(r0), "=r"(r1) : "r"(a));
}
__device__ __forceinline__ void ldsm_x2t(u32& r0, u32& r1, u32 a) {
    asm volatile("ldmatrix.sync.aligned.m8n8.x2.trans.shared.b16 {%0,%1}, [%2];"
                 : "=r"(r0), "=r"(r1) : "r"(a));
}
__device__ __forceinline__ void mma_bf16(float* c, const u32* a, const u32* b) {
    asm volatile(
        "mma.sync.aligned.m16n8k16.row.col.f32.bf16.bf16.f32 "
        "{%0,%1,%2,%3}, {%4,%5,%6,%7}, {%8,%9}, {%0,%1,%2,%3};"
        : "+f"(c[0]), "+f"(c[1]), "+f"(c[2]), "+f"(c[3])
        : "r"(a[0]), "r"(a[1]), "r"(a[2]), "r"(a[3]), "r"(b[0]), "r"(b[1]));
}

// ---------------------------------------------------------------------------
// GEMM: D[m,n] = sum_k A[m,k]*B'[k,n] via bf16x3 (Ahi*Bhi + Ahi*Blo + Alo*Bhi)
//   BT=true : B stored [N][K] row-major (k-major rows)        -> ldmatrix
//   BT=false: B stored [K][N] row-major (n-major rows)        -> ldmatrix.trans
//   MODE 0: hi/lo bf16 out + bias;   MODE 2: fp32 out * alpha
// CTA tile 128x128, BK=32, 3-stage cp.async pipeline, 256 threads (8 warps 2x4)
// ---------------------------------------------------------------------------
#define BM 128
#define BN 128
#define BKK 32
#define APITCH 40            // bf16 units per A row (32 + 8 pad)
#define ABYTES (BM * APITCH * 2)            // 10240
#define BPITCH_T 40
#define BBYTES_T (BN * BPITCH_T * 2)        // 10240
#define BPITCH_N 136         // bf16 units per B row (128 + 8 pad), NN layout
#define BBYTES_N (BKK * BPITCH_N * 2)       // 8704

template <int MODE, bool BT>
__global__ void __launch_bounds__(256, 1)
gemm_mma(const bf16* __restrict__ Ahi, const bf16* __restrict__ Alo,
         const bf16* __restrict__ Bhi, const bf16* __restrict__ Blo,
         const float* __restrict__ bias,
         bf16* __restrict__ C0, bf16* __restrict__ C1, float* __restrict__ Cf,
         int lda, int ldb, int ldc, int K, float alpha,
         long long sA, long long sB, long long sC)
{
    constexpr int BBYTES = BT ? BBYTES_T : BBYTES_N;
    constexpr int OFF_ALO = ABYTES;
    constexpr int OFF_BHI = 2 * ABYTES;
    constexpr int OFF_BLO = 2 * ABYTES + BBYTES;
    constexpr int STAGE   = 2 * ABYTES + 2 * BBYTES;

    extern __shared__ char smem[];
    const u32 sb = smem_u32(smem);

    const int tid  = threadIdx.x;
    const int wid  = tid >> 5, lane = tid & 31;
    const int wm   = wid & 1, wn = wid >> 1;      // 2 x 4 warp grid
    const long long z = blockIdx.z;
    Ahi += z * sA; Alo += z * sA;
    Bhi += z * sB; Blo += z * sB;

    const int m0 = blockIdx.y * BM;
    const int n0 = blockIdx.x * BN;

    // ---- loader geometry ----
    // A: 512 chunks of 16B: r = idx>>2 (row), c = idx&3 (16B chunk)
    const int ar0 = tid >> 2, ac = (tid & 3) * 8;
    // B(BT): same shape.  B(NN): r = idx>>4 (k-row 0..31), c = idx&15
    const int br0 = BT ? (tid >> 2) : (tid >> 4);
    const int bc  = BT ? ((tid & 3) * 8) : ((tid & 15) * 8);

    auto load_stage = [&](int t) {
        const long long kb = (long long)t * BKK;
        const u32 st = sb + (u32)((t % 3) * STAGE);
#pragma unroll
        for (int i = 0; i < 2; i++) {
            const int r = ar0 + i * 64;
            const u32 d = st + (u32)(r * APITCH + ac) * 2;
            const long long g = (long long)(m0 + r) * lda + kb + ac;
            CP_ASYNC16(d, Ahi + g);
            CP_ASYNC16(d + OFF_ALO, Alo + g);
        }
        if (BT) {
#pragma unroll
            for (int i = 0; i < 2; i++) {
                const int r = br0 + i * 64;
                const u32 d = st + OFF_BHI + (u32)(r * BPITCH_T + bc) * 2;
                const long long g = (long long)(n0 + r) * ldb + kb + bc;
                CP_ASYNC16(d, Bhi + g);
                CP_ASYNC16(d + BBYTES, Blo + g);
            }
        } else {
#pragma unroll
            for (int i = 0; i < 2; i++) {
                const int r = br0 + i * 16;
                const u32 d = st + OFF_BHI + (u32)(r * BPITCH_N + bc) * 2;
                const long long g = (kb + r) * (long long)ldb + n0 + bc;
                CP_ASYNC16(d, Bhi + g);
                CP_ASYNC16(d + BBYTES, Blo + g);
            }
        }
    };

    // ---- ldmatrix per-lane offsets ----
    // A x4: lane -> (row within 16, k offset 0/8)
    const int a_lr = (lane & 7) + ((lane >> 3) & 1) * 8;
    const int a_lk = (lane >> 4) * 8;
    u32 a_off[4];
#pragma unroll
    for (int mt = 0; mt < 4; mt++)
        a_off[mt] = (u32)((wm * 64 + mt * 16 + a_lr) * APITCH + a_lk) * 2;

    const int l16 = lane & 15;
    u32 b_off[4];
    if (BT) {
        const int b_nr = l16 & 7, b_k = (l16 >> 3) * 8;
#pragma unroll
        for (int nt = 0; nt < 4; nt++)
            b_off[nt] = (u32)((wn * 32 + nt * 8 + b_nr) * BPITCH_T + b_k) * 2;
    } else {
        const int b_kr = (l16 & 7) + (l16 >> 3) * 8;
#pragma unroll
        for (int nt = 0; nt < 4; nt++)
            b_off[nt] = (u32)(b_kr * BPITCH_N + wn * 32 + nt * 8) * 2;
    }

    float acc[4][4][4];
#pragma unroll
    for (int i = 0; i < 4; i++)
#pragma unroll
        for (int j = 0; j < 4; j++)
#pragma unroll
            for (int v = 0; v < 4; v++) acc[i][j][v] = 0.0f;

    const int nst = K / BKK;

    load_stage(0); CP_COMMIT();
    load_stage(1); CP_COMMIT();

    for (int t = 0; t < nst; t++) {
        CP_WAIT1();
        __syncthreads();
        if (t + 2 < nst) load_stage(t + 2);
        CP_COMMIT();

        const u32 st  = sb + (u32)((t % 3) * STAGE);
        const u32 bAh = st, bAl = st + OFF_ALO;
        const u32 bBh = st + OFF_BHI, bBl = st + OFF_BLO;

#pragma unroll
        for (int kk = 0; kk < 2; kk++) {
            const u32 ak = (u32)(kk * 32);                       // +16 bf16 in k
            const u32 bk = BT ? (u32)(kk * 32) : (u32)(kk * 16 * BPITCH_N * 2);
            u32 ah[4][4], al[4][4], bh[4][2], bl[4][2];
#pragma unroll
            for (int mt = 0; mt < 4; mt++) {
                ldsm_x4(ah[mt][0], ah[mt][1], ah[mt][2], ah[mt][3], bAh + a_off[mt] + ak);
                ldsm_x4(al[mt][0], al[mt][1], al[mt][2], al[mt][3], bAl + a_off[mt] + ak);
            }
#pragma unroll
            for (int nt = 0; nt < 4; nt++) {
                if (BT) {
                    ldsm_x2(bh[nt][0], bh[nt][1], bBh + b_off[nt] + bk);
                    ldsm_x2(bl[nt][0], bl[nt][1], bBl + b_off[nt] + bk);
                } else {
                    ldsm_x2t(bh[nt][0], bh[nt][1], bBh + b_off[nt] + bk);
                    ldsm_x2t(bl[nt][0], bl[nt][1], bBl + b_off[nt] + bk);
                }
            }
#pragma unroll
            for (int mt = 0; mt < 4; mt++)
#pragma unroll
                for (int nt = 0; nt < 4; nt++) {
                    mma_bf16(acc[mt][nt], ah[mt], bh[nt]);
                    mma_bf16(acc[mt][nt], ah[mt], bl[nt]);
                    mma_bf16(acc[mt][nt], al[mt], bh[nt]);
                }
        }
        __syncthreads();
    }

    // ---- epilogue ----
    const int gr = lane >> 2, gc = (lane & 3) * 2;
#pragma unroll
    for (int mt = 0; mt < 4; mt++) {
#pragma unroll
        for (int nt = 0; nt < 4; nt++) {
            const int m_ = m0 + wm * 64 + mt * 16 + gr;
            const int n_ = n0 + wn * 32 + nt * 8 + gc;
            const float* a4 = acc[mt][nt];
            if (MODE == 0) {
                const float b0 = bias[n_], b1 = bias[n_ + 1];
#pragma unroll
                for (int h = 0; h < 2; h++) {
                    const float v0 = a4[2 * h]     + b0;
                    const float v1 = a4[2 * h + 1] + b1;
                    const bf16 h0 = __float2bfloat16(v0);
                    const bf16 h1 = __float2bfloat16(v1);
                    const bf16 l0 = __float2bfloat16(v0 - __bfloat162float(h0));
                    const bf16 l1 = __float2bfloat16(v1 - __bfloat162float(h1));
                    const long long o = (long long)(m_ + 8 * h) * ldc + n_;
                    *(__nv_bfloat162*)(C0 + o) = __nv_bfloat162(h0, h1);
                    *(__nv_bfloat162*)(C1 + o) = __nv_bfloat162(l0, l1);
                }
            } else {
                float* Cz = Cf + z * sC;
#pragma unroll
                for (int h = 0; h < 2; h++) {
                    const long long o = (long long)(m_ + 8 * h) * ldc + n_;
                    float2 v = make_float2(a4[2 * h] * alpha, a4[2 * h + 1] * alpha);
                    *(float2*)(Cz + o) = v;
                }
            }
        }
    }
}

// ---------------------------------------------------------------------------
// fp32 -> (hi, lo) bf16 split
// ---------------------------------------------------------------------------
__global__ void __launch_bounds__(256)
split_f32(const float4* __restrict__ in, bf16* __restrict__ hi,
          bf16* __restrict__ lo)
{
    const long long i = (long long)blockIdx.x * 256 + threadIdx.x;
    const float4 v = in[i];
    const bf16 h0 = __float2bfloat16(v.x), h1 = __float2bfloat16(v.y);
    const bf16 h2 = __float2bfloat16(v.z), h3 = __float2bfloat16(v.w);
    const bf16 l0 = __float2bfloat16(v.x - __bfloat162float(h0));
    const bf16 l1 = __float2bfloat16(v.y - __bfloat162float(h1));
    const bf16 l2 = __float2bfloat16(v.z - __bfloat162float(h2));
    const bf16 l3 = __float2bfloat16(v.w - __bfloat162float(h3));
    *(__nv_bfloat162*)&hi[i * 4]     = __nv_bfloat162(h0, h1);
    *(__nv_bfloat162*)&hi[i * 4 + 2] = __nv_bfloat162(h2, h3);
    *(__nv_bfloat162*)&lo[i * 4]     = __nv_bfloat162(l0, l1);
    *(__nv_bfloat162*)&lo[i * 4 + 2] = __nv_bfloat162(l2, l3);
}

// W [F=1024, H=1024] -> W^T split hi/lo [H, F]
__global__ void wt_split(const float* __restrict__ W, bf16* __restrict__ Thi,
                         bf16* __restrict__ Tlo)
{
    __shared__ float ts[32][33];
    const int tx = threadIdx.x, ty = threadIdx.y;
    ts[ty][tx] = W[(long long)(blockIdx.y * 32 + ty) * 1024 + blockIdx.x * 32 + tx];
    __syncthreads();
    const float x = ts[tx][ty];
    const long long o = (long long)(blockIdx.x * 32 + ty) * 1024 + blockIdx.y * 32 + tx;
    const bf16 h = __float2bfloat16(x);
    Thi[o] = h;
    Tlo[o] = __float2bfloat16(x - __bfloat162float(h));
}

// ---------------------------------------------------------------------------
// Mask dtype detection (bool may arrive as u8/i32/f32)
// ---------------------------------------------------------------------------
__global__ void detect_mask_kernel(const unsigned char* __restrict__ m)
{
    __shared__ int bad_i32, bad_f32;
    if (threadIdx.x == 0) { bad_i32 = 0; bad_f32 = 0; }
    __syncthreads();
    const unsigned int* w = (const unsigned int*)m;
    for (int i = threadIdx.x; i < 2048; i += 256) {
        unsigned int x = w[i];
        if (x != 0u && x != 1u)          bad_i32 = 1;
        if (x != 0u && x != 0x3F800000u) bad_f32 = 1;
    }
    __syncthreads();
    if (threadIdx.x == 0)
        g_mask_mode = bad_i32 ? (bad_f32 ? 0 : 2) : 1;
}

// ---------------------------------------------------------------------------
// Masked softmax over rows of S [B*TQ, 2048] -> P hi/lo bf16
// ---------------------------------------------------------------------------
__global__ void __launch_bounds__(256)
softmax_kernel(const float* __restrict__ S, const void* __restrict__ maskv,
               bf16* __restrict__ Phi, bf16* __restrict__ Plo)
{
    const int TK = 2048;
    const long long base = (long long)blockIdx.x * TK;
    const float* s = S + base;
    const int tid  = threadIdx.x;
    const int mode = g_mask_mode;

    float v[8];
    bool  keep[8];
#pragma unroll
    for (int i = 0; i < 8; i++) {
        const int idx = tid + i * 256;
        v[i] = s[idx];
        bool kp;
        if (mode == 1)      kp = ((const int*)maskv)[base + idx] != 0;
        else if (mode == 2) kp = ((const float*)maskv)[base + idx] != 0.0f;
        else                kp = ((const unsigned char*)maskv)[base + idx] != 0;
        keep[i] = kp;
    }

    float mx = -3.0e38f;
#pragma unroll
    for (int i = 0; i < 8; i++)
        if (keep[i]) mx = fmaxf(mx, v[i]);

    __shared__ float red[8];
#pragma unroll
    for (int o = 16; o > 0; o >>= 1)
        mx = fmaxf(mx, __shfl_xor_sync(0xffffffffu, mx, o));
    if ((tid & 31) == 0) red[tid >> 5] = mx;
    __syncthreads();
    float bm = red[0];
#pragma unroll
    for (int i = 1; i < 8; i++) bm = fmaxf(bm, red[i]);

    float sum = 0.0f;
#pragma unroll
    for (int i = 0; i < 8; i++) {
        const float e = keep[i] ? __expf(v[i] - bm) : 0.0f;
        v[i] = e;
        sum += e;
    }
#pragma unroll
    for (int o = 16; o > 0; o >>= 1)
        sum += __shfl_xor_sync(0xffffffffu, sum, o);
    __syncthreads();
    if ((tid & 31) == 0) red[tid >> 5] = sum;
    __syncthreads();
    float ts = 0.0f;
#pragma unroll
    for (int i = 0; i < 8; i++) ts += red[i];

    const float inv = 1.0f / ts;
#pragma unroll
    for (int i = 0; i < 8; i++) {
        const float p = v[i] * inv;
        const bf16 h = __float2bfloat16(p);
        const bf16 l = __float2bfloat16(p - __bfloat162float(h));
        const long long o = base + tid + i * 256;
        Phi[o] = h;
        Plo[o] = l;
    }
}

// ---------------------------------------------------------------------------
// kernel_launch
// ---------------------------------------------------------------------------
extern "C" void kernel_launch(void* const* d_in, const int* in_sizes, int n_in,
                              void* d_out, int out_size)
{
    (void)in_sizes; (void)n_in; (void)out_size;

    const float* query = (const float*)d_in[0];
    const float* enc   = (const float*)d_in[1];
    const unsigned char* mask = (const unsigned char*)d_in[2];
    const float* Wq = (const float*)d_in[3];
    const float* bq = (const float*)d_in[4];
    const float* Wk = (const float*)d_in[5];
    const float* bk = (const float*)d_in[6];
    const float* Wv = (const float*)d_in[7];
    const float* bv = (const float*)d_in[8];
    float* out = (float*)d_out;

    bf16 *Ehi, *Elo, *Xhi, *Xlo;
    bf16 *Wqh, *Wql, *Wkh, *Wkl, *Wvh, *Wvl;
    bf16 *Qh, *Ql, *Kh, *Kl, *Vh, *Vl, *Ph, *Pl;
    float* Sp;
    cudaGetSymbolAddress((void**)&Ehi, g_Ehi);   cudaGetSymbolAddress((void**)&Elo, g_Elo);
    cudaGetSymbolAddress((void**)&Xhi, g_Xhi);   cudaGetSymbolAddress((void**)&Xlo, g_Xlo);
    cudaGetSymbolAddress((void**)&Wqh, g_Wq_hi); cudaGetSymbolAddress((void**)&Wql, g_Wq_lo);
    cudaGetSymbolAddress((void**)&Wkh, g_Wk_hi); cudaGetSymbolAddress((void**)&Wkl, g_Wk_lo);
    cudaGetSymbolAddress((void**)&Wvh, g_Wv_hi); cudaGetSymbolAddress((void**)&Wvl, g_Wv_lo);
    cudaGetSymbolAddress((void**)&Qh,  g_Qhi);   cudaGetSymbolAddress((void**)&Ql,  g_Qlo);
    cudaGetSymbolAddress((void**)&Kh,  g_Khi);   cudaGetSymbolAddress((void**)&Kl,  g_Klo);
    cudaGetSymbolAddress((void**)&Vh,  g_Vhi);   cudaGetSymbolAddress((void**)&Vl,  g_Vlo);
    cudaGetSymbolAddress((void**)&Ph,  g_Phi);   cudaGetSymbolAddress((void**)&Pl,  g_Plo);
    cudaGetSymbolAddress((void**)&Sp,  g_S);

    constexpr int SMEM_T = 3 * (2 * ABYTES + 2 * BBYTES_T);   // 122880
    constexpr int SMEM_N = 3 * (2 * ABYTES + 2 * BBYTES_N);   // 113664
    cudaFuncSetAttribute(gemm_mma<0, true>,  cudaFuncAttributeMaxDynamicSharedMemorySize, SMEM_T);
    cudaFuncSetAttribute(gemm_mma<2, true>,  cudaFuncAttributeMaxDynamicSharedMemorySize, SMEM_T);
    cudaFuncSetAttribute(gemm_mma<2, false>, cudaFuncAttributeMaxDynamicSharedMemorySize, SMEM_N);

    const int T = 2048;

    // 1) split inputs to bf16 hi/lo
    split_f32<<<16384, 256>>>((const float4*)enc,   Ehi, Elo);
    split_f32<<<16384, 256>>>((const float4*)query, Xhi, Xlo);

    // 2) transpose+split weights
    dim3 wtg(32, 32), wtb(32, 32);
    wt_split<<<wtg, wtb>>>(Wq, Wqh, Wql);
    wt_split<<<wtg, wtb>>>(Wk, Wkh, Wkl);
    wt_split<<<wtg, wtb>>>(Wv, Wvh, Wvl);

    detect_mask_kernel<<<1, 256>>>(mask);

    // 3) projections: [16384,1024] @ Wt[1024(n),1024(k)]  (BT layout)
    dim3 gp(1024 / BN, 16384 / BM, 1);
    gemm_mma<0, true><<<gp, 256, SMEM_T>>>(Ehi, Elo, Wkh, Wkl, bk, Kh, Kl, nullptr,
                                           1024, 1024, 1024, 1024, 1.0f, 0, 0, 0);
    gemm_mma<0, true><<<gp, 256, SMEM_T>>>(Ehi, Elo, Wvh, Wvl, bv, Vh, Vl, nullptr,
                                           1024, 1024, 1024, 1024, 1.0f, 0, 0, 0);
    gemm_mma<0, true><<<gp, 256, SMEM_T>>>(Xhi, Xlo, Wqh, Wql, bq, Qh, Ql, nullptr,
                                           1024, 1024, 1024, 1024, 1.0f, 0, 0, 0);

    // 4) scores: per batch S = (Q K^T) / 32     (B = K, [TK][H] = BT layout)
    dim3 gs(T / BN, T / BM, 8);
    gemm_mma<2, true><<<gs, 256, SMEM_T>>>(Qh, Ql, Kh, Kl, nullptr, nullptr, nullptr, Sp,
                                           1024, 1024, 2048, 1024, 0.03125f,
                                           2048LL * 1024, 2048LL * 1024, 2048LL * 2048);

    // 5) masked softmax -> P hi/lo
    softmax_kernel<<<8 * T, 256>>>(Sp, (const void*)mask, Ph, Pl);

    // 6) output: per batch O = P @ V   (B = V, [TK(k)][H(n)] = NN layout, ldmatrix.trans)
    dim3 go(1024 / BN, T / BM, 8);
    gemm_mma<2, false><<<go, 256, SMEM_N>>>(Ph, Pl, Vh, Vl, nullptr, nullptr, nullptr, out,
                                            2048, 1024, 1024, 2048, 1.0f,
                                            2048LL * 2048, 2048LL * 1024, 2048LL * 1024);
}

// round 6
// speedup vs baseline: 2.1486x; 1.0530x over previous
#include <cuda_runtime.h>
#include <cuda_bf16.h>

typedef __nv_bfloat16 bf16;
typedef unsigned int u32;
typedef unsigned long long u64;

// ---------------------------------------------------------------------------
// Problem constants: B=8, TQ=TK=2048, F=1024, H=1024
// ---------------------------------------------------------------------------
#define MTOT (16384LL * 1024)

static __device__ bf16  g_Ehi[MTOT],  g_Elo[MTOT];
static __device__ bf16  g_Xhi[MTOT],  g_Xlo[MTOT];
static __device__ bf16  g_Wq_hi[1024*1024], g_Wq_lo[1024*1024];
static __device__ bf16  g_Wk_hi[1024*1024], g_Wk_lo[1024*1024];
static __device__ bf16  g_Wv_hi[1024*1024], g_Wv_lo[1024*1024];
static __device__ bf16  g_Qhi[MTOT],  g_Qlo[MTOT];
static __device__ bf16  g_Khi[MTOT],  g_Klo[MTOT];
static __device__ bf16  g_Vhi[MTOT],  g_Vlo[MTOT];          // V [b*2048+t][1024]
static __device__ float g_S[8LL * 2048 * 2048];
static __device__ bf16  g_Phi[8LL * 2048 * 2048], g_Plo[8LL * 2048 * 2048];
static __device__ int   g_mask_mode;

// ---------------------------------------------------------------------------
// PTX helpers (sm_80-era features; legal under generic compute_103 target)
// ---------------------------------------------------------------------------
__device__ __forceinline__ u32 smem_u32(const void* p) {
    u32 a;
    asm("{ .reg .u64 t; cvta.to.shared.u64 t, %1; cvt.u32.u64 %0, t; }"
        : "=r"(a) : "l"(p));
    return a;
}
#define CP_ASYNC16(dst, src) \
    asm volatile("cp.async.cg.shared.global [%0], [%1], 16;" \
                 :: "r"(dst), "l"(src) : "memory")
#define CP_COMMIT() asm volatile("cp.async.commit_group;" ::: "memory")
#define CP_WAIT1()  asm volatile("cp.async.wait_group 1;" ::: "memory")

__device__ __forceinline__ void ldsm_x4(u32& r0, u32& r1, u32& r2, u32& r3, u32 a) {
    asm volatile("ldmatrix.sync.aligned.m8n8.x4.shared.b16 {%0,%1,%2,%3}, [%4];"
                 : "=r"(r0), "=r"(r1), "=r"(r2), "=r"(r3) : "r"(a));
}
__device__ __forceinline__ void ldsm_x2(u32& r0, u32& r1, u32 a) {
    asm volatile("ldmatrix.sync.aligned.m8n8.x2.shared.b16 {%0,%1}, [%2];"
                 : "=r"(r0), "=r"(r1) : "r"(a));
}
__device__ __forceinline__ void ldsm_x2t(u32& r0, u32& r1, u32 a) {
    asm volatile("ldmatrix.sync.aligned.m8n8.x2.trans.shared.b16 {%0,%1}, [%2];"
                 : "=r"(r0), "=r"(r1) : "r"(a));
}
__device__ __forceinline__ void mma_bf16(float* c, const u32* a, const u32* b) {
    asm volatile(
        "mma.sync.aligned.m16n8k16.row.col.f32.bf16.bf16.f32 "
        "{%0,%1,%2,%3}, {%4,%5,%6,%7}, {%8,%9}, {%0,%1,%2,%3};"
        : "+f"(c[0]), "+f"(c[1]), "+f"(c[2]), "+f"(c[3])
        : "r"(a[0]), "r"(a[1]), "r"(a[2]), "r"(a[3]), "r"(b[0]), "r"(b[1]));
}

// ---------------------------------------------------------------------------
// GEMM: D[m,n] = sum_k A[m,k]*B'[k,n] via bf16x3 (Ahi*Bhi + Ahi*Blo + Alo*Bhi)
//   BT=true : B stored [N][K] (k-major rows)   -> ldmatrix
//   BT=false: B stored [K][N] (n-major rows)   -> ldmatrix.trans
//   MODE 0: hi/lo bf16 out + bias;   MODE 2: fp32 out * alpha
// CTA tile 128x128, BK=64, 3-stage cp.async pipeline, register-level frag
// double-buffering across the 4 kk-steps, 256 threads (8 warps, 2x4 grid).
// ---------------------------------------------------------------------------
#define BM 128
#define BN 128
#define BKK 64
#define APITCH 72                            // 64 + 8 pad (bf16 units)
#define ABYTES (BM * APITCH * 2)             // 18432
#define BPITCH_T 72
#define BBYTES_T (BN * BPITCH_T * 2)         // 18432
#define BPITCH_N 136                         // 128 + 8 pad
#define BBYTES_N (BKK * BPITCH_N * 2)        // 17408

template <int MODE, bool BT>
__global__ void __launch_bounds__(256, 1)
gemm_mma(const bf16* __restrict__ Ahi, const bf16* __restrict__ Alo,
         const bf16* __restrict__ Bhi, const bf16* __restrict__ Blo,
         const float* __restrict__ bias,
         bf16* __restrict__ C0, bf16* __restrict__ C1, float* __restrict__ Cf,
         int lda, int ldb, int ldc, int K, float alpha,
         long long sA, long long sB, long long sC)
{
    constexpr int BBYTES  = BT ? BBYTES_T : BBYTES_N;
    constexpr int OFF_ALO = ABYTES;
    constexpr int OFF_BHI = 2 * ABYTES;
    constexpr int OFF_BLO = 2 * ABYTES + BBYTES;
    constexpr int STAGE   = 2 * ABYTES + 2 * BBYTES;

    extern __shared__ char smem[];
    const u32 sb = smem_u32(smem);

    const int tid  = threadIdx.x;
    const int wid  = tid >> 5, lane = tid & 31;
    const int wm   = wid & 1, wn = wid >> 1;          // 2 x 4 warp grid
    const long long z = blockIdx.z;
    Ahi += z * sA; Alo += z * sA;
    Bhi += z * sB; Blo += z * sB;

    const int m0 = blockIdx.y * BM;
    const int n0 = blockIdx.x * BN;

    // ---- loader geometry (BK=64) ----
    // A/B(BT): 128 rows x 64 cols: r0 = tid>>2 (0..63) -> rows r0, r0+64;
    //          ac = (tid&3)*16 elems; 16B chunks at ac, ac+8.
    const int ar0 = tid >> 2, ac = (tid & 3) * 16;
    // B(NN): 64 rows x 128 cols: r0 = tid>>4 (0..15) -> rows +0/16/32/48;
    //        c = (tid&15)*8 elems.
    const int nr0 = tid >> 4, nc = (tid & 15) * 8;

    auto load_stage = [&](int t) {
        const long long kb = (long long)t * BKK;
        const u32 st = sb + (u32)((t % 3) * STAGE);
#pragma unroll
        for (int i = 0; i < 2; i++) {
            const int r = ar0 + i * 64;
            const long long g = (long long)(m0 + r) * lda + kb + ac;
            const u32 d = st + (u32)(r * APITCH + ac) * 2;
            CP_ASYNC16(d,                Ahi + g);
            CP_ASYNC16(d + 16,           Ahi + g + 8);
            CP_ASYNC16(d + OFF_ALO,      Alo + g);
            CP_ASYNC16(d + OFF_ALO + 16, Alo + g + 8);
        }
        if (BT) {
#pragma unroll
            for (int i = 0; i < 2; i++) {
                const int r = ar0 + i * 64;
                const long long g = (long long)(n0 + r) * ldb + kb + ac;
                const u32 d = st + OFF_BHI + (u32)(r * BPITCH_T + ac) * 2;
                CP_ASYNC16(d,               Bhi + g);
                CP_ASYNC16(d + 16,          Bhi + g + 8);
                CP_ASYNC16(d + BBYTES,      Blo + g);
                CP_ASYNC16(d + BBYTES + 16, Blo + g + 8);
            }
        } else {
#pragma unroll
            for (int i = 0; i < 4; i++) {
                const int r = nr0 + i * 16;
                const long long g = (kb + r) * (long long)ldb + n0 + nc;
                const u32 d = st + OFF_BHI + (u32)(r * BPITCH_N + nc) * 2;
                CP_ASYNC16(d,          Bhi + g);
                CP_ASYNC16(d + BBYTES, Blo + g);
            }
        }
    };

    // ---- ldmatrix per-lane offsets ----
    const int a_lr = (lane & 7) + ((lane >> 3) & 1) * 8;
    const int a_lk = (lane >> 4) * 8;
    u32 a_off[4];
#pragma unroll
    for (int mt = 0; mt < 4; mt++)
        a_off[mt] = (u32)((wm * 64 + mt * 16 + a_lr) * APITCH + a_lk) * 2;

    const int l16 = lane & 15;
    u32 b_off[4];
    if (BT) {
        const int b_nr = l16 & 7, b_k = (l16 >> 3) * 8;
#pragma unroll
        for (int nt = 0; nt < 4; nt++)
            b_off[nt] = (u32)((wn * 32 + nt * 8 + b_nr) * BPITCH_T + b_k) * 2;
    } else {
        const int b_kr = l16;      // 16 k-rows
#pragma unroll
        for (int nt = 0; nt < 4; nt++)
            b_off[nt] = (u32)(b_kr * BPITCH_N + wn * 32 + nt * 8) * 2;
    }

    float acc[4][4][4];
#pragma unroll
    for (int i = 0; i < 4; i++)
#pragma unroll
        for (int j = 0; j < 4; j++)
#pragma unroll
            for (int v = 0; v < 4; v++) acc[i][j][v] = 0.0f;

    // double-buffered fragments
    u32 ah[2][4][4], al[2][4][4], bh[2][4][2], bl[2][4][2];

    const int nst = K / BKK;

    load_stage(0); CP_COMMIT();
    load_stage(1); CP_COMMIT();

    for (int t = 0; t < nst; t++) {
        CP_WAIT1();
        __syncthreads();
        if (t + 2 < nst) load_stage(t + 2);
        CP_COMMIT();

        const u32 st  = sb + (u32)((t % 3) * STAGE);
        const u32 bAh = st, bAl = st + OFF_ALO;
        const u32 bBh = st + OFF_BHI, bBl = st + OFF_BLO;

        // prime frag buffer 0 (kk = 0)
        {
            const u32 ak = 0, bk = 0;
#pragma unroll
            for (int mt = 0; mt < 4; mt++) {
                ldsm_x4(ah[0][mt][0], ah[0][mt][1], ah[0][mt][2], ah[0][mt][3],
                        bAh + a_off[mt] + ak);
                ldsm_x4(al[0][mt][0], al[0][mt][1], al[0][mt][2], al[0][mt][3],
                        bAl + a_off[mt] + ak);
            }
#pragma unroll
            for (int nt = 0; nt < 4; nt++) {
                if (BT) {
                    ldsm_x2(bh[0][nt][0], bh[0][nt][1], bBh + b_off[nt] + bk);
                    ldsm_x2(bl[0][nt][0], bl[0][nt][1], bBl + b_off[nt] + bk);
                } else {
                    ldsm_x2t(bh[0][nt][0], bh[0][nt][1], bBh + b_off[nt] + bk);
                    ldsm_x2t(bl[0][nt][0], bl[0][nt][1], bBl + b_off[nt] + bk);
                }
            }
        }

#pragma unroll
        for (int kk = 0; kk < 4; kk++) {
            const int cur = kk & 1, nxt = cur ^ 1;
            if (kk < 3) {
                const u32 ak = (u32)((kk + 1) * 32);   // 16 bf16 in k
                const u32 bk = BT ? (u32)((kk + 1) * 32)
                                  : (u32)((kk + 1) * 16 * BPITCH_N * 2);
#pragma unroll
                for (int mt = 0; mt < 4; mt++) {
                    ldsm_x4(ah[nxt][mt][0], ah[nxt][mt][1], ah[nxt][mt][2],
                            ah[nxt][mt][3], bAh + a_off[mt] + ak);
                    ldsm_x4(al[nxt][mt][0], al[nxt][mt][1], al[nxt][mt][2],
                            al[nxt][mt][3], bAl + a_off[mt] + ak);
                }
#pragma unroll
                for (int nt = 0; nt < 4; nt++) {
                    if (BT) {
                        ldsm_x2(bh[nxt][nt][0], bh[nxt][nt][1], bBh + b_off[nt] + bk);
                        ldsm_x2(bl[nxt][nt][0], bl[nxt][nt][1], bBl + b_off[nt] + bk);
                    } else {
                        ldsm_x2t(bh[nxt][nt][0], bh[nxt][nt][1], bBh + b_off[nt] + bk);
                        ldsm_x2t(bl[nxt][nt][0], bl[nxt][nt][1], bBl + b_off[nt] + bk);
                    }
                }
            }
#pragma unroll
            for (int mt = 0; mt < 4; mt++)
#pragma unroll
                for (int nt = 0; nt < 4; nt++) {
                    mma_bf16(acc[mt][nt], ah[cur][mt], bh[cur][nt]);
                    mma_bf16(acc[mt][nt], ah[cur][mt], bl[cur][nt]);
                    mma_bf16(acc[mt][nt], al[cur][mt], bh[cur][nt]);
                }
        }
    }

    // ---- epilogue ----
    const int gr = lane >> 2, gc = (lane & 3) * 2;
#pragma unroll
    for (int mt = 0; mt < 4; mt++) {
#pragma unroll
        for (int nt = 0; nt < 4; nt++) {
            const int m_ = m0 + wm * 64 + mt * 16 + gr;
            const int n_ = n0 + wn * 32 + nt * 8 + gc;
            const float* a4 = acc[mt][nt];
            if (MODE == 0) {
                const float b0 = bias[n_], b1 = bias[n_ + 1];
#pragma unroll
                for (int h = 0; h < 2; h++) {
                    const float v0 = a4[2 * h]     + b0;
                    const float v1 = a4[2 * h + 1] + b1;
                    const bf16 h0 = __float2bfloat16(v0);
                    const bf16 h1 = __float2bfloat16(v1);
                    const bf16 l0 = __float2bfloat16(v0 - __bfloat162float(h0));
                    const bf16 l1 = __float2bfloat16(v1 - __bfloat162float(h1));
                    const long long o = (long long)(m_ + 8 * h) * ldc + n_;
                    *(__nv_bfloat162*)(C0 + o) = __nv_bfloat162(h0, h1);
                    *(__nv_bfloat162*)(C1 + o) = __nv_bfloat162(l0, l1);
                }
            } else {
                float* Cz = Cf + z * sC;
#pragma unroll
                for (int h = 0; h < 2; h++) {
                    const long long o = (long long)(m_ + 8 * h) * ldc + n_;
                    float2 v = make_float2(a4[2 * h] * alpha, a4[2 * h + 1] * alpha);
                    *(float2*)(Cz + o) = v;
                }
            }
        }
    }
}

// ---------------------------------------------------------------------------
// fp32 -> (hi, lo) bf16 split
// ---------------------------------------------------------------------------
__global__ void __launch_bounds__(256)
split_f32(const float4* __restrict__ in, bf16* __restrict__ hi,
          bf16* __restrict__ lo)
{
    const long long i = (long long)blockIdx.x * 256 + threadIdx.x;
    const float4 v = in[i];
    const bf16 h0 = __float2bfloat16(v.x), h1 = __float2bfloat16(v.y);
    const bf16 h2 = __float2bfloat16(v.z), h3 = __float2bfloat16(v.w);
    const bf16 l0 = __float2bfloat16(v.x - __bfloat162float(h0));
    const bf16 l1 = __float2bfloat16(v.y - __bfloat162float(h1));
    const bf16 l2 = __float2bfloat16(v.z - __bfloat162float(h2));
    const bf16 l3 = __float2bfloat16(v.w - __bfloat162float(h3));
    *(__nv_bfloat162*)&hi[i * 4]     = __nv_bfloat162(h0, h1);
    *(__nv_bfloat162*)&hi[i * 4 + 2] = __nv_bfloat162(h2, h3);
    *(__nv_bfloat162*)&lo[i * 4]     = __nv_bfloat162(l0, l1);
    *(__nv_bfloat162*)&lo[i * 4 + 2] = __nv_bfloat162(l2, l3);
}

// W [F=1024, H=1024] -> W^T split hi/lo [H, F]
__global__ void wt_split(const float* __restrict__ W, bf16* __restrict__ Thi,
                         bf16* __restrict__ Tlo)
{
    __shared__ float ts[32][33];
    const int tx = threadIdx.x, ty = threadIdx.y;
    ts[ty][tx] = W[(long long)(blockIdx.y * 32 + ty) * 1024 + blockIdx.x * 32 + tx];
    __syncthreads();
    const float x = ts[tx][ty];
    const long long o = (long long)(blockIdx.x * 32 + ty) * 1024 + blockIdx.y * 32 + tx;
    const bf16 h = __float2bfloat16(x);
    Thi[o] = h;
    Tlo[o] = __float2bfloat16(x - __bfloat162float(h));
}

// ---------------------------------------------------------------------------
// Mask dtype detection (bool may arrive as u8/i32/f32)
// ---------------------------------------------------------------------------
__global__ void detect_mask_kernel(const unsigned char* __restrict__ m)
{
    __shared__ int bad_i32, bad_f32;
    if (threadIdx.x == 0) { bad_i32 = 0; bad_f32 = 0; }
    __syncthreads();
    const unsigned int* w = (const unsigned int*)m;
    for (int i = threadIdx.x; i < 2048; i += 256) {
        unsigned int x = w[i];
        if (x != 0u && x != 1u)          bad_i32 = 1;
        if (x != 0u && x != 0x3F800000u) bad_f32 = 1;
    }
    __syncthreads();
    if (threadIdx.x == 0)
        g_mask_mode = bad_i32 ? (bad_f32 ? 0 : 2) : 1;
}

// ---------------------------------------------------------------------------
// Masked softmax over rows of S [B*TQ, 2048] -> P hi/lo bf16
// ---------------------------------------------------------------------------
__global__ void __launch_bounds__(256)
softmax_kernel(const float* __restrict__ S, const void* __restrict__ maskv,
               bf16* __restrict__ Phi, bf16* __restrict__ Plo)
{
    const int TK = 2048;
    const long long base = (long long)blockIdx.x * TK;
    const float* s = S + base;
    const int tid  = threadIdx.x;
    const int mode = g_mask_mode;

    float v[8];
    bool  keep[8];
#pragma unroll
    for (int i = 0; i < 8; i++) {
        const int idx = tid + i * 256;
        v[i] = s[idx];
        bool kp;
        if (mode == 1)      kp = ((const int*)maskv)[base + idx] != 0;
        else if (mode == 2) kp = ((const float*)maskv)[base + idx] != 0.0f;
        else                kp = ((const unsigned char*)maskv)[base + idx] != 0;
        keep[i] = kp;
    }

    float mx = -3.0e38f;
#pragma unroll
    for (int i = 0; i < 8; i++)
        if (keep[i]) mx = fmaxf(mx, v[i]);

    __shared__ float red[8];
#pragma unroll
    for (int o = 16; o > 0; o >>= 1)
        mx = fmaxf(mx, __shfl_xor_sync(0xffffffffu, mx, o));
    if ((tid & 31) == 0) red[tid >> 5] = mx;
    __syncthreads();
    float bm = red[0];
#pragma unroll
    for (int i = 1; i < 8; i++) bm = fmaxf(bm, red[i]);

    float sum = 0.0f;
#pragma unroll
    for (int i = 0; i < 8; i++) {
        const float e = keep[i] ? __expf(v[i] - bm) : 0.0f;
        v[i] = e;
        sum += e;
    }
#pragma unroll
    for (int o = 16; o > 0; o >>= 1)
        sum += __shfl_xor_sync(0xffffffffu, sum, o);
    __syncthreads();
    if ((tid & 31) == 0) red[tid >> 5] = sum;
    __syncthreads();
    float ts = 0.0f;
#pragma unroll
    for (int i = 0; i < 8; i++) ts += red[i];

    const float inv = 1.0f / ts;
#pragma unroll
    for (int i = 0; i < 8; i++) {
        const float p = v[i] * inv;
        const bf16 h = __float2bfloat16(p);
        const bf16 l = __float2bfloat16(p - __bfloat162float(h));
        const long long o = base + tid + i * 256;
        Phi[o] = h;
        Plo[o] = l;
    }
}

// ---------------------------------------------------------------------------
// kernel_launch
// ---------------------------------------------------------------------------
extern "C" void kernel_launch(void* const* d_in, const int* in_sizes, int n_in,
                              void* d_out, int out_size)
{
    (void)in_sizes; (void)n_in; (void)out_size;

    const float* query = (const float*)d_in[0];
    const float* enc   = (const float*)d_in[1];
    const unsigned char* mask = (const unsigned char*)d_in[2];
    const float* Wq = (const float*)d_in[3];
    const float* bq = (const float*)d_in[4];
    const float* Wk = (const float*)d_in[5];
    const float* bk = (const float*)d_in[6];
    const float* Wv = (const float*)d_in[7];
    const float* bv = (const float*)d_in[8];
    float* out = (float*)d_out;

    bf16 *Ehi, *Elo, *Xhi, *Xlo;
    bf16 *Wqh, *Wql, *Wkh, *Wkl, *Wvh, *Wvl;
    bf16 *Qh, *Ql, *Kh, *Kl, *Vh, *Vl, *Ph, *Pl;
    float* Sp;
    cudaGetSymbolAddress((void**)&Ehi, g_Ehi);   cudaGetSymbolAddress((void**)&Elo, g_Elo);
    cudaGetSymbolAddress((void**)&Xhi, g_Xhi);   cudaGetSymbolAddress((void**)&Xlo, g_Xlo);
    cudaGetSymbolAddress((void**)&Wqh, g_Wq_hi); cudaGetSymbolAddress((void**)&Wql, g_Wq_lo);
    cudaGetSymbolAddress((void**)&Wkh, g_Wk_hi); cudaGetSymbolAddress((void**)&Wkl, g_Wk_lo);
    cudaGetSymbolAddress((void**)&Wvh, g_Wv_hi); cudaGetSymbolAddress((void**)&Wvl, g_Wv_lo);
    cudaGetSymbolAddress((void**)&Qh,  g_Qhi);   cudaGetSymbolAddress((void**)&Ql,  g_Qlo);
    cudaGetSymbolAddress((void**)&Kh,  g_Khi);   cudaGetSymbolAddress((void**)&Kl,  g_Klo);
    cudaGetSymbolAddress((void**)&Vh,  g_Vhi);   cudaGetSymbolAddress((void**)&Vl,  g_Vlo);
    cudaGetSymbolAddress((void**)&Ph,  g_Phi);   cudaGetSymbolAddress((void**)&Pl,  g_Plo);
    cudaGetSymbolAddress((void**)&Sp,  g_S);

    constexpr int SMEM_T = 3 * (2 * ABYTES + 2 * BBYTES_T);   // 221184
    constexpr int SMEM_N = 3 * (2 * ABYTES + 2 * BBYTES_N);   // 215040
    cudaFuncSetAttribute(gemm_mma<0, true>,  cudaFuncAttributeMaxDynamicSharedMemorySize, SMEM_T);
    cudaFuncSetAttribute(gemm_mma<2, true>,  cudaFuncAttributeMaxDynamicSharedMemorySize, SMEM_T);
    cudaFuncSetAttribute(gemm_mma<2, false>, cudaFuncAttributeMaxDynamicSharedMemorySize, SMEM_N);

    const int T = 2048;

    // 1) split inputs to bf16 hi/lo
    split_f32<<<16384, 256>>>((const float4*)enc,   Ehi, Elo);
    split_f32<<<16384, 256>>>((const float4*)query, Xhi, Xlo);

    // 2) transpose+split weights
    dim3 wtg(32, 32), wtb(32, 32);
    wt_split<<<wtg, wtb>>>(Wq, Wqh, Wql);
    wt_split<<<wtg, wtb>>>(Wk, Wkh, Wkl);
    wt_split<<<wtg, wtb>>>(Wv, Wvh, Wvl);

    detect_mask_kernel<<<1, 256>>>(mask);

    // 3) projections: [16384,1024] @ Wt[1024(n),1024(k)]  (BT layout)
    dim3 gp(1024 / BN, 16384 / BM, 1);
    gemm_mma<0, true><<<gp, 256, SMEM_T>>>(Ehi, Elo, Wkh, Wkl, bk, Kh, Kl, nullptr,
                                           1024, 1024, 1024, 1024, 1.0f, 0, 0, 0);
    gemm_mma<0, true><<<gp, 256, SMEM_T>>>(Ehi, Elo, Wvh, Wvl, bv, Vh, Vl, nullptr,
                                           1024, 1024, 1024, 1024, 1.0f, 0, 0, 0);
    gemm_mma<0, true><<<gp, 256, SMEM_T>>>(Xhi, Xlo, Wqh, Wql, bq, Qh, Ql, nullptr,
                                           1024, 1024, 1024, 1024, 1.0f, 0, 0, 0);

    // 4) scores: per batch S = (Q K^T) / 32     (B = K, [TK][H] = BT layout)
    dim3 gs(T / BN, T / BM, 8);
    gemm_mma<2, true><<<gs, 256, SMEM_T>>>(Qh, Ql, Kh, Kl, nullptr, nullptr, nullptr, Sp,
                                           1024, 1024, 2048, 1024, 0.03125f,
                                           2048LL * 1024, 2048LL * 1024, 2048LL * 2048);

    // 5) masked softmax -> P hi/lo
    softmax_kernel<<<8 * T, 256>>>(Sp, (const void*)mask, Ph, Pl);

    // 6) output: per batch O = P @ V   (B = V, [TK(k)][H(n)] = NN layout, ldmatrix.trans)
    dim3 go(1024 / BN, T / BM, 8);
    gemm_mma<2, false><<<go, 256, SMEM_N>>>(Ph, Pl, Vh, Vl, nullptr, nullptr, nullptr, out,
                                            2048, 1024, 1024, 2048, 1.0f,
                                            2048LL * 2048, 2048LL * 1024, 2048LL * 1024);
}